// round 7
// baseline (speedup 1.0000x reference)
#include <cuda_runtime.h>

#define GS     16
#define NPAIR  136          // 16*17/2 lower-triangular pairs
#define NACC   152          // 136 pair sums + 16 channel sums
#define GROUPS 32
#define BATCH  32
#define HW     3136         // 56*56
#define HW4    784          // HW/4 (float4 units)
#define CH     512
#define CHUNK  64           // float4 positions staged per chunk
#define NCHUNK 13           // ceil(784/64)

typedef unsigned long long ull;

static __device__ float d_acc[GROUPS][NACC];   // pair sums + channel sums
static __device__ float d_Linv[GROUPS][NPAIR]; // packed lower-triangular Linv
static __device__ float d_bias[CH];            // Linv @ mean, per channel

// ---- packed f32x2 helpers (Blackwell) --------------------------------------
__device__ __forceinline__ void fma2(ull& d, ull a, ull b) {
    asm("fma.rn.f32x2 %0, %1, %2, %0;" : "+l"(d) : "l"(a), "l"(b));
}
__device__ __forceinline__ void add2(ull& d, ull a) {
    asm("add.rn.f32x2 %0, %0, %1;" : "+l"(d) : "l"(a));
}
__device__ __forceinline__ float unpack_add(ull v) {
    float lo, hi;
    asm("mov.b64 {%0,%1}, %2;" : "=f"(lo), "=f"(hi) : "l"(v));
    return lo + hi;
}

// ---------------------------------------------------------------------------
__global__ void zero_kernel() {
    int i = blockIdx.x * blockDim.x + threadIdx.x;
    if (i < GROUPS * NACC) ((float*)d_acc)[i] = 0.f;
}

// ---------------------------------------------------------------------------
// Stats v5: double-buffered smem staging, each gmem float4 read exactly once.
// 512 threads / 16 warps; chunk = 64 float4 positions; ONE barrier per chunk.
// LDGs for chunk k+1 issue at the top of iter k (full-chunk latency overlap).
//   warps 0-3  : diag quad q (10 pairs + 4 sums), 2 positions per lane
//   warps 4-15 : 6 cross quad-blocks x 2 warps (16 pairs), 1 position per lane
__global__ void __launch_bounds__(512, 2) stats_kernel(const float* __restrict__ x) {
    const int g = blockIdx.x & 31;
    const int b = blockIdx.x >> 5;
    const float4* in = (const float4*)(x + ((size_t)b * CH + (size_t)g * GS) * HW);

    __shared__ float4 buf[2][GS][CHUNK];   // 2 x 16 KB

    const int tid  = threadIdx.x;
    const int wid  = tid >> 5;
    const int lane = tid & 31;

    // staging coords for this thread (2 float4 per thread per chunk)
    const int s_ch0 = tid >> 6,        s_p0 = tid & 63;          // idx = tid
    const int s_ch1 = (tid + 512) >> 6, s_p1 = (tid + 512) & 63; // idx = tid+512

    // role decode
    const int QI[6] = {1, 2, 3, 2, 3, 3};
    const int QJ[6] = {0, 0, 0, 1, 1, 2};
    const bool diag = (wid < 4);
    const int  q    = wid;                         // diag quad
    const int  cb   = diag ? 0 : ((wid - 4) >> 1); // cross block 0..5
    const int  half = diag ? 0 : ((wid - 4) & 1);  // cross half 0/1
    const int  qi   = diag ? q : QI[cb];
    const int  qj   = diag ? q : QJ[cb];

    ull acc[16];
#pragma unroll
    for (int k = 0; k < 16; k++) acc[k] = 0ull;

    const float4 Z = make_float4(0.f, 0.f, 0.f, 0.f);
    float4 st0, st1;

    // prefetch chunk 0
    st0 = (s_p0 < HW4) ? __ldg(in + (size_t)s_ch0 * HW4 + s_p0) : Z;
    st1 = (s_p1 < HW4) ? __ldg(in + (size_t)s_ch1 * HW4 + s_p1) : Z;
    buf[0][s_ch0][s_p0] = st0;
    buf[0][s_ch1][s_p1] = st1;
    __syncthreads();

    for (int k = 0; k < NCHUNK; k++) {
        const int cur = k & 1;
        // issue next chunk's gmem loads FIRST (overlap with full chunk compute)
        if (k + 1 < NCHUNK) {
            const int base = (k + 1) * CHUNK;
            const int p0 = base + s_p0, p1 = base + s_p1;
            st0 = (p0 < HW4) ? __ldg(in + (size_t)s_ch0 * HW4 + p0) : Z;
            st1 = (p1 < HW4) ? __ldg(in + (size_t)s_ch1 * HW4 + p1) : Z;
        }

        if (diag) {
            // 2 positions per lane: lane and lane+32
#pragma unroll
            for (int p2 = 0; p2 < 2; p2++) {
                const int pos = lane + p2 * 32;
                ulonglong2 v[4];
#pragma unroll
                for (int c = 0; c < 4; c++)
                    v[c] = *(const ulonglong2*)&buf[cur][q * 4 + c][pos];
#pragma unroll
                for (int i = 0; i < 4; i++) {
#pragma unroll
                    for (int j = 0; j <= i; j++) {
                        const int kk = i * (i + 1) / 2 + j;
                        fma2(acc[kk], v[i].x, v[j].x);
                        fma2(acc[kk], v[i].y, v[j].y);
                    }
                    add2(acc[10 + i], v[i].x);
                    add2(acc[10 + i], v[i].y);
                }
            }
        } else {
            const int pos = half * 32 + lane;
            ulonglong2 u[4], w[4];
#pragma unroll
            for (int c = 0; c < 4; c++) {
                u[c] = *(const ulonglong2*)&buf[cur][qi * 4 + c][pos];
                w[c] = *(const ulonglong2*)&buf[cur][qj * 4 + c][pos];
            }
#pragma unroll
            for (int i = 0; i < 4; i++)
#pragma unroll
                for (int j = 0; j < 4; j++) {
                    const int kk = i * 4 + j;
                    fma2(acc[kk], u[i].x, w[j].x);
                    fma2(acc[kk], u[i].y, w[j].y);
                }
        }

        // park next chunk into the other buffer, then one barrier
        if (k + 1 < NCHUNK) {
            buf[cur ^ 1][s_ch0][s_p0] = st0;
            buf[cur ^ 1][s_ch1][s_p1] = st1;
        }
        __syncthreads();
    }

    // reduce + emit
    float r[16];
#pragma unroll
    for (int k = 0; k < 16; k++) r[k] = unpack_add(acc[k]);
#pragma unroll
    for (int k = 0; k < 16; k++) {
#pragma unroll
        for (int off = 16; off > 0; off >>= 1)
            r[k] += __shfl_xor_sync(0xffffffffu, r[k], off);
    }
    if (lane == 0) {
        if (diag) {
            for (int i = 0; i < 4; i++) {
                for (int j = 0; j <= i; j++) {
                    const int gi = q * 4 + i, gj = q * 4 + j;
                    atomicAdd(&d_acc[g][gi * (gi + 1) / 2 + gj], r[i * (i + 1) / 2 + j]);
                }
                atomicAdd(&d_acc[g][NPAIR + q * 4 + i], r[10 + i]);
            }
        } else {
            for (int i = 0; i < 4; i++)
                for (int j = 0; j < 4; j++) {
                    const int gi = qi * 4 + i, gj = qj * 4 + j;
                    atomicAdd(&d_acc[g][gi * (gi + 1) / 2 + gj], r[i * 4 + j]);
                }
        }
    }
}

// ---------------------------------------------------------------------------
// Solve: one block per group, 16 threads, everything in shared memory, fp64.
__global__ void __launch_bounds__(16) solve_kernel() {
    const int g = blockIdx.x;
    const int t = threadIdx.x;
    __shared__ double P[GS][GS + 1];
    __shared__ double L[GS][GS + 1];
    __shared__ double V[GS][GS + 1];
    __shared__ double m[GS];

    const double Nd   = (double)BATCH * (double)HW;
    const double EPSd = 1e-3;
    const unsigned MASK = 0xffffu;

    m[t] = (double)d_acc[g][NPAIR + t] / Nd;
    __syncwarp(MASK);

    for (int j = 0; j < GS; j++) {
        const int i_ = t > j ? t : j, j_ = t > j ? j : t;
        double c = (double)d_acc[g][i_ * (i_ + 1) / 2 + j_] / Nd - m[t] * m[j];
        c *= (1.0 - EPSd);
        if (t == j) c += EPSd;
        P[t][j] = c;
    }
    __syncwarp(MASK);

    for (int j = 0; j < GS; j++) {
        if (t == j) {
            double s = P[j][j];
            for (int k = 0; k < j; k++) s -= L[j][k] * L[j][k];
            L[j][j] = sqrt(s);
        }
        __syncwarp(MASK);
        if (t > j) {
            double s = P[t][j];
            for (int k = 0; k < j; k++) s -= L[t][k] * L[j][k];
            L[t][j] = s / L[j][j];
        }
        __syncwarp(MASK);
    }

    V[t][t] = 1.0 / L[t][t];
    for (int i = t + 1; i < GS; i++) {
        double s = 0.0;
        for (int k = t; k < i; k++) s += L[i][k] * V[k][t];
        V[i][t] = -s / L[i][i];
    }
    __syncwarp(MASK);

    double bsum = 0.0;
    for (int j = 0; j <= t; j++) {
        d_Linv[g][t * (t + 1) / 2 + j] = (float)V[t][j];
        bsum += V[t][j] * m[j];
    }
    d_bias[g * GS + t] = (float)bsum;
}

// ---------------------------------------------------------------------------
// Apply (unchanged, proven 66us / 68% DRAM):
// out_i = sum_{j<=i} Linv_ij * x_j - bias_i, float4, streaming stores.
__global__ void __launch_bounds__(256, 2) apply_kernel(const float* __restrict__ x,
                                                       float* __restrict__ out) {
    const int g = blockIdx.x & 31;
    const int b = blockIdx.x >> 5;

    __shared__ float Ls[NPAIR];
    __shared__ float bs[GS];
    if (threadIdx.x < NPAIR) Ls[threadIdx.x] = d_Linv[g][threadIdx.x];
    if (threadIdx.x < GS)    bs[threadIdx.x] = d_bias[g * GS + threadIdx.x];
    __syncthreads();

    const size_t off = ((size_t)b * CH + (size_t)g * GS) * HW;
    const float4* in = (const float4*)(x + off);
    float4*       op = (float4*)(out + off);

    for (int pos = threadIdx.x; pos < HW4; pos += 256) {
        float4 v[GS];
#pragma unroll
        for (int c = 0; c < GS; c++) v[c] = in[(size_t)c * HW4 + pos];
#pragma unroll
        for (int i = 0; i < GS; i++) {
            const float bias = bs[i];
            float4 a;
            a.x = -bias; a.y = -bias; a.z = -bias; a.w = -bias;
#pragma unroll
            for (int j = 0; j <= i; j++) {
                const float f = Ls[i * (i + 1) / 2 + j];
                a.x = fmaf(f, v[j].x, a.x);
                a.y = fmaf(f, v[j].y, a.y);
                a.z = fmaf(f, v[j].z, a.z);
                a.w = fmaf(f, v[j].w, a.w);
            }
            __stcs(&op[(size_t)i * HW4 + pos], a);
        }
    }
}

// ---------------------------------------------------------------------------
extern "C" void kernel_launch(void* const* d_in, const int* in_sizes, int n_in,
                              void* d_out, int out_size) {
    const float* x   = (const float*)d_in[0];
    float*       out = (float*)d_out;

    zero_kernel<<<(GROUPS * NACC + 255) / 256, 256>>>();
    stats_kernel<<<GROUPS * BATCH, 512>>>(x);
    solve_kernel<<<GROUPS, 16>>>();
    apply_kernel<<<GROUPS * BATCH, 256>>>(x, out);
}

// round 8
// speedup vs baseline: 1.0348x; 1.0348x over previous
#include <cuda_runtime.h>
#include <cstdint>

#define GS     16
#define NPAIR  136          // 16*17/2 lower-triangular pairs
#define NACC   152          // 136 pair sums + 16 channel sums
#define GROUPS 32
#define BATCH  32
#define HW     3136         // 56*56
#define HW4    784          // HW/4 (float4 units)
#define CH     512
#define CHUNK  64           // float4 positions staged per chunk
#define NCHUNK 13           // ceil(784/64)
#define STATS_T 640         // threads (20 warps)

typedef unsigned long long ull;

static __device__ float d_acc[GROUPS][NACC];   // pair sums + channel sums
static __device__ float d_Linv[GROUPS][NPAIR]; // packed lower-triangular Linv
static __device__ float d_bias[CH];            // Linv @ mean, per channel

// ---- packed f32x2 helpers (Blackwell) --------------------------------------
__device__ __forceinline__ void fma2(ull& d, ull a, ull b) {
    asm("fma.rn.f32x2 %0, %1, %2, %0;" : "+l"(d) : "l"(a), "l"(b));
}
__device__ __forceinline__ void add2(ull& d, ull a) {
    asm("add.rn.f32x2 %0, %0, %1;" : "+l"(d) : "l"(a));
}
__device__ __forceinline__ float unpack_add(ull v) {
    float lo, hi;
    asm("mov.b64 {%0,%1}, %2;" : "=f"(lo), "=f"(hi) : "l"(v));
    return lo + hi;
}

// ---- cp.async helpers -------------------------------------------------------
__device__ __forceinline__ uint32_t smem_u32(const void* p) {
    return (uint32_t)__cvta_generic_to_shared(p);
}
__device__ __forceinline__ void cp16(uint32_t dst, const void* src) {
    asm volatile("cp.async.cg.shared.global [%0], [%1], 16;" :: "r"(dst), "l"(src));
}
__device__ __forceinline__ void cp_commit() {
    asm volatile("cp.async.commit_group;" ::: "memory");
}
template <int N>
__device__ __forceinline__ void cp_wait() {
    asm volatile("cp.async.wait_group %0;" :: "n"(N) : "memory");
}

// ---------------------------------------------------------------------------
__global__ void zero_kernel() {
    int i = blockIdx.x * blockDim.x + threadIdx.x;
    if (i < GROUPS * NACC) ((float*)d_acc)[i] = 0.f;
}

// ---------------------------------------------------------------------------
// Stats v6: cp.async double-buffered smem staging. Each gmem float4 is read
// exactly once (DRAM floor ~34us). 640 threads / 20 warps, no register
// staging (LDGSTS), accumulators stay in registers (no launch_bounds cap).
//   warps 0-7  : diag quad q=wid/2 (10 pairs + 4 sums), 32 positions/warp
//   warps 8-19 : cross quad-block (16 pairs), 2 warps each, 32 pos/warp
__global__ void __launch_bounds__(STATS_T) stats_kernel(const float* __restrict__ x) {
    const int g = blockIdx.x & 31;
    const int b = blockIdx.x >> 5;
    const float4* in = (const float4*)(x + ((size_t)b * CH + (size_t)g * GS) * HW);

    __shared__ float4 buf[2][GS][CHUNK];   // 2 x 16 KB

    const int tid  = threadIdx.x;
    const int wid  = tid >> 5;
    const int lane = tid & 31;

    // staging: 1024 slots/chunk; thread t -> slot t, and slot t+640 if t<384
    const int s_ch0 = tid >> 6,          s_p0 = tid & 63;
    const int s_ch1 = (tid + STATS_T) >> 6, s_p1 = (tid + STATS_T) & 63;
    const bool two  = (tid + STATS_T) < GS * CHUNK;

    // role decode
    const int QI[6] = {1, 2, 3, 2, 3, 3};
    const int QJ[6] = {0, 0, 0, 1, 1, 2};
    const bool diag = (wid < 8);
    const int  q    = wid >> 1;                    // diag quad (0..3)
    const int  dh   = wid & 1;                     // diag half
    const int  cb   = diag ? 0 : ((wid - 8) >> 1); // cross block 0..5
    const int  chf  = diag ? 0 : ((wid - 8) & 1);  // cross half
    const int  qi   = diag ? q : QI[cb];
    const int  qj   = diag ? q : QJ[cb];
    const int  pos  = (diag ? dh : chf) * 32 + lane;  // position within chunk

    ull acc[16];
#pragma unroll
    for (int k = 0; k < 16; k++) acc[k] = 0ull;

    // ---- stage one chunk: cp.async valid slots, STS zeros for tail ----------
    auto stage = [&](int c, int bufsel) {
        float4* d0 = &buf[bufsel][s_ch0][s_p0];
        const int p0 = c * CHUNK + s_p0;
        if (p0 < HW4) cp16(smem_u32(d0), in + (size_t)s_ch0 * HW4 + p0);
        else          *d0 = make_float4(0.f, 0.f, 0.f, 0.f);
        if (two) {
            float4* d1 = &buf[bufsel][s_ch1][s_p1];
            const int p1 = c * CHUNK + s_p1;
            if (p1 < HW4) cp16(smem_u32(d1), in + (size_t)s_ch1 * HW4 + p1);
            else          *d1 = make_float4(0.f, 0.f, 0.f, 0.f);
        }
        cp_commit();
    };

    stage(0, 0);   // prologue

    for (int k = 0; k < NCHUNK; k++) {
        const int cur = k & 1;
        if (k + 1 < NCHUNK) { stage(k + 1, cur ^ 1); cp_wait<1>(); }
        else                { cp_wait<0>(); }
        __syncthreads();   // chunk k resident & visible to all warps

        if (diag) {
            ulonglong2 v[4];
#pragma unroll
            for (int c = 0; c < 4; c++)
                v[c] = *(const ulonglong2*)&buf[cur][q * 4 + c][pos];
#pragma unroll
            for (int i = 0; i < 4; i++) {
#pragma unroll
                for (int j = 0; j <= i; j++) {
                    const int kk = i * (i + 1) / 2 + j;
                    fma2(acc[kk], v[i].x, v[j].x);
                    fma2(acc[kk], v[i].y, v[j].y);
                }
                add2(acc[10 + i], v[i].x);
                add2(acc[10 + i], v[i].y);
            }
        } else {
            ulonglong2 u[4], w[4];
#pragma unroll
            for (int c = 0; c < 4; c++) {
                u[c] = *(const ulonglong2*)&buf[cur][qi * 4 + c][pos];
                w[c] = *(const ulonglong2*)&buf[cur][qj * 4 + c][pos];
            }
#pragma unroll
            for (int i = 0; i < 4; i++)
#pragma unroll
                for (int j = 0; j < 4; j++) {
                    const int kk = i * 4 + j;
                    fma2(acc[kk], u[i].x, w[j].x);
                    fma2(acc[kk], u[i].y, w[j].y);
                }
        }
        __syncthreads();   // compute done before buf[cur] is re-staged
    }

    // reduce + emit
    float r[16];
#pragma unroll
    for (int k = 0; k < 16; k++) r[k] = unpack_add(acc[k]);
#pragma unroll
    for (int k = 0; k < 16; k++) {
#pragma unroll
        for (int off = 16; off > 0; off >>= 1)
            r[k] += __shfl_xor_sync(0xffffffffu, r[k], off);
    }
    if (lane == 0) {
        if (diag) {
            for (int i = 0; i < 4; i++) {
                for (int j = 0; j <= i; j++) {
                    const int gi = q * 4 + i, gj = q * 4 + j;
                    atomicAdd(&d_acc[g][gi * (gi + 1) / 2 + gj], r[i * (i + 1) / 2 + j]);
                }
                atomicAdd(&d_acc[g][NPAIR + q * 4 + i], r[10 + i]);
            }
        } else {
            for (int i = 0; i < 4; i++)
                for (int j = 0; j < 4; j++) {
                    const int gi = qi * 4 + i, gj = qj * 4 + j;
                    atomicAdd(&d_acc[g][gi * (gi + 1) / 2 + gj], r[i * 4 + j]);
                }
        }
    }
}

// ---------------------------------------------------------------------------
// Solve: one block per group, 16 threads, everything in shared memory, fp64.
__global__ void __launch_bounds__(16) solve_kernel() {
    const int g = blockIdx.x;
    const int t = threadIdx.x;
    __shared__ double P[GS][GS + 1];
    __shared__ double L[GS][GS + 1];
    __shared__ double V[GS][GS + 1];
    __shared__ double m[GS];

    const double Nd   = (double)BATCH * (double)HW;
    const double EPSd = 1e-3;
    const unsigned MASK = 0xffffu;

    m[t] = (double)d_acc[g][NPAIR + t] / Nd;
    __syncwarp(MASK);

    for (int j = 0; j < GS; j++) {
        const int i_ = t > j ? t : j, j_ = t > j ? j : t;
        double c = (double)d_acc[g][i_ * (i_ + 1) / 2 + j_] / Nd - m[t] * m[j];
        c *= (1.0 - EPSd);
        if (t == j) c += EPSd;
        P[t][j] = c;
    }
    __syncwarp(MASK);

    for (int j = 0; j < GS; j++) {
        if (t == j) {
            double s = P[j][j];
            for (int k = 0; k < j; k++) s -= L[j][k] * L[j][k];
            L[j][j] = sqrt(s);
        }
        __syncwarp(MASK);
        if (t > j) {
            double s = P[t][j];
            for (int k = 0; k < j; k++) s -= L[t][k] * L[j][k];
            L[t][j] = s / L[j][j];
        }
        __syncwarp(MASK);
    }

    V[t][t] = 1.0 / L[t][t];
    for (int i = t + 1; i < GS; i++) {
        double s = 0.0;
        for (int k = t; k < i; k++) s += L[i][k] * V[k][t];
        V[i][t] = -s / L[i][i];
    }
    __syncwarp(MASK);

    double bsum = 0.0;
    for (int j = 0; j <= t; j++) {
        d_Linv[g][t * (t + 1) / 2 + j] = (float)V[t][j];
        bsum += V[t][j] * m[j];
    }
    d_bias[g * GS + t] = (float)bsum;
}

// ---------------------------------------------------------------------------
// Apply (unchanged, proven ~66us / 69% DRAM):
// out_i = sum_{j<=i} Linv_ij * x_j - bias_i, float4, streaming stores.
__global__ void __launch_bounds__(256, 2) apply_kernel(const float* __restrict__ x,
                                                       float* __restrict__ out) {
    const int g = blockIdx.x & 31;
    const int b = blockIdx.x >> 5;

    __shared__ float Ls[NPAIR];
    __shared__ float bs[GS];
    if (threadIdx.x < NPAIR) Ls[threadIdx.x] = d_Linv[g][threadIdx.x];
    if (threadIdx.x < GS)    bs[threadIdx.x] = d_bias[g * GS + threadIdx.x];
    __syncthreads();

    const size_t off = ((size_t)b * CH + (size_t)g * GS) * HW;
    const float4* in = (const float4*)(x + off);
    float4*       op = (float4*)(out + off);

    for (int pos = threadIdx.x; pos < HW4; pos += 256) {
        float4 v[GS];
#pragma unroll
        for (int c = 0; c < GS; c++) v[c] = in[(size_t)c * HW4 + pos];
#pragma unroll
        for (int i = 0; i < GS; i++) {
            const float bias = bs[i];
            float4 a;
            a.x = -bias; a.y = -bias; a.z = -bias; a.w = -bias;
#pragma unroll
            for (int j = 0; j <= i; j++) {
                const float f = Ls[i * (i + 1) / 2 + j];
                a.x = fmaf(f, v[j].x, a.x);
                a.y = fmaf(f, v[j].y, a.y);
                a.z = fmaf(f, v[j].z, a.z);
                a.w = fmaf(f, v[j].w, a.w);
            }
            __stcs(&op[(size_t)i * HW4 + pos], a);
        }
    }
}

// ---------------------------------------------------------------------------
extern "C" void kernel_launch(void* const* d_in, const int* in_sizes, int n_in,
                              void* d_out, int out_size) {
    const float* x   = (const float*)d_in[0];
    float*       out = (float*)d_out;

    zero_kernel<<<(GROUPS * NACC + 255) / 256, 256>>>();
    stats_kernel<<<GROUPS * BATCH, STATS_T>>>(x);
    solve_kernel<<<GROUPS, 16>>>();
    apply_kernel<<<GROUPS * BATCH, 256>>>(x, out);
}

// round 9
// speedup vs baseline: 1.0671x; 1.0312x over previous
#include <cuda_runtime.h>
#include <cstdint>

#define GS     16
#define NPAIR  136          // 16*17/2 lower-triangular pairs
#define NACC   152          // 136 pair sums + 16 channel sums
#define GROUPS 32
#define BATCH  32
#define HW     3136         // 56*56
#define HW4    784          // HW/4 (float4 units)
#define CH     512
#define CHUNK  64           // float4 positions staged per chunk
#define NCHUNK 13           // ceil(784/64)
#define DEPTH  3            // ring buffers (2 chunks in flight while computing)
#define STATS_T 640         // threads (20 warps)

typedef unsigned long long ull;

static __device__ float d_acc[GROUPS][NACC];   // pair sums + channel sums
static __device__ float d_Linv[GROUPS][NPAIR]; // packed lower-triangular Linv
static __device__ float d_bias[CH];            // Linv @ mean, per channel

// ---- packed f32x2 helpers (Blackwell) --------------------------------------
__device__ __forceinline__ void fma2(ull& d, ull a, ull b) {
    asm("fma.rn.f32x2 %0, %1, %2, %0;" : "+l"(d) : "l"(a), "l"(b));
}
__device__ __forceinline__ void add2(ull& d, ull a) {
    asm("add.rn.f32x2 %0, %0, %1;" : "+l"(d) : "l"(a));
}
__device__ __forceinline__ float unpack_add(ull v) {
    float lo, hi;
    asm("mov.b64 {%0,%1}, %2;" : "=f"(lo), "=f"(hi) : "l"(v));
    return lo + hi;
}

// ---- cp.async helpers -------------------------------------------------------
__device__ __forceinline__ uint32_t smem_u32(const void* p) {
    return (uint32_t)__cvta_generic_to_shared(p);
}
__device__ __forceinline__ void cp16(uint32_t dst, const void* src) {
    asm volatile("cp.async.cg.shared.global [%0], [%1], 16;" :: "r"(dst), "l"(src));
}
__device__ __forceinline__ void cp_commit() {
    asm volatile("cp.async.commit_group;" ::: "memory");
}
template <int N>
__device__ __forceinline__ void cp_wait() {
    asm volatile("cp.async.wait_group %0;" :: "n"(N) : "memory");
}

// ---------------------------------------------------------------------------
__global__ void zero_kernel() {
    int i = blockIdx.x * blockDim.x + threadIdx.x;
    if (i < GROUPS * NACC) ((float*)d_acc)[i] = 0.f;
}

// ---------------------------------------------------------------------------
// Stats v7: cp.async DEPTH-3 ring (2 chunks = 32KB/block in flight while
// computing -> DMA stream saturates its DRAM fair-share; R8 was depth-1 and
// latency-bound at ~27 B/cyc/SM). Each gmem float4 read exactly once.
// 640 threads / 20 warps:
//   warps 0-7  : diag quad q=wid/2 (10 pairs + 4 sums), 32 positions/warp
//   warps 8-19 : cross quad-block (16 pairs), 2 warps each, 32 pos/warp
__global__ void __launch_bounds__(STATS_T) stats_kernel(const float* __restrict__ x) {
    const int g = blockIdx.x & 31;
    const int b = blockIdx.x >> 5;
    const float4* in = (const float4*)(x + ((size_t)b * CH + (size_t)g * GS) * HW);

    __shared__ float4 buf[DEPTH][GS][CHUNK];   // 3 x 16 KB = 48 KB

    const int tid  = threadIdx.x;
    const int wid  = tid >> 5;
    const int lane = tid & 31;

    // staging: 1024 slots/chunk; thread t -> slot t, and slot t+640 if valid
    const int s_ch0 = tid >> 6,             s_p0 = tid & 63;
    const int s_ch1 = (tid + STATS_T) >> 6, s_p1 = (tid + STATS_T) & 63;
    const bool two  = (tid + STATS_T) < GS * CHUNK;

    // role decode
    const int QI[6] = {1, 2, 3, 2, 3, 3};
    const int QJ[6] = {0, 0, 0, 1, 1, 2};
    const bool diag = (wid < 8);
    const int  q    = wid >> 1;
    const int  dh   = wid & 1;
    const int  cb   = diag ? 0 : ((wid - 8) >> 1);
    const int  chf  = diag ? 0 : ((wid - 8) & 1);
    const int  qi   = diag ? q : QI[cb];
    const int  qj   = diag ? q : QJ[cb];
    const int  pos  = (diag ? dh : chf) * 32 + lane;

    ull acc[16];
#pragma unroll
    for (int k = 0; k < 16; k++) acc[k] = 0ull;

    auto stage = [&](int c, int bufsel) {
        float4* d0 = &buf[bufsel][s_ch0][s_p0];
        const int p0 = c * CHUNK + s_p0;
        if (p0 < HW4) cp16(smem_u32(d0), in + (size_t)s_ch0 * HW4 + p0);
        else          *d0 = make_float4(0.f, 0.f, 0.f, 0.f);
        if (two) {
            float4* d1 = &buf[bufsel][s_ch1][s_p1];
            const int p1 = c * CHUNK + s_p1;
            if (p1 < HW4) cp16(smem_u32(d1), in + (size_t)s_ch1 * HW4 + p1);
            else          *d1 = make_float4(0.f, 0.f, 0.f, 0.f);
        }
        cp_commit();
    };

    // prologue: 3 chunks in flight
    stage(0, 0);
    stage(1, 1);
    stage(2, 2);

    for (int k = 0; k < NCHUNK; k++) {
        const int cur = k % DEPTH;
        // groups complete in order: ensure chunk k's group is done.
        if (k <= NCHUNK - 3)      cp_wait<2>();
        else if (k == NCHUNK - 2) cp_wait<1>();
        else                      cp_wait<0>();
        __syncthreads();   // all threads' chunk-k copies landed

        if (diag) {
            ulonglong2 v[4];
#pragma unroll
            for (int c = 0; c < 4; c++)
                v[c] = *(const ulonglong2*)&buf[cur][q * 4 + c][pos];
#pragma unroll
            for (int i = 0; i < 4; i++) {
#pragma unroll
                for (int j = 0; j <= i; j++) {
                    const int kk = i * (i + 1) / 2 + j;
                    fma2(acc[kk], v[i].x, v[j].x);
                    fma2(acc[kk], v[i].y, v[j].y);
                }
                add2(acc[10 + i], v[i].x);
                add2(acc[10 + i], v[i].y);
            }
        } else {
            ulonglong2 u[4], w[4];
#pragma unroll
            for (int c = 0; c < 4; c++) {
                u[c] = *(const ulonglong2*)&buf[cur][qi * 4 + c][pos];
                w[c] = *(const ulonglong2*)&buf[cur][qj * 4 + c][pos];
            }
#pragma unroll
            for (int i = 0; i < 4; i++)
#pragma unroll
                for (int j = 0; j < 4; j++) {
                    const int kk = i * 4 + j;
                    fma2(acc[kk], u[i].x, w[j].x);
                    fma2(acc[kk], u[i].y, w[j].y);
                }
        }
        __syncthreads();   // everyone done reading slot before it is re-staged

        if (k + DEPTH < NCHUNK) stage(k + DEPTH, cur);
    }

    // reduce + emit
    float r[16];
#pragma unroll
    for (int k = 0; k < 16; k++) r[k] = unpack_add(acc[k]);
#pragma unroll
    for (int k = 0; k < 16; k++) {
#pragma unroll
        for (int off = 16; off > 0; off >>= 1)
            r[k] += __shfl_xor_sync(0xffffffffu, r[k], off);
    }
    if (lane == 0) {
        if (diag) {
            for (int i = 0; i < 4; i++) {
                for (int j = 0; j <= i; j++) {
                    const int gi = q * 4 + i, gj = q * 4 + j;
                    atomicAdd(&d_acc[g][gi * (gi + 1) / 2 + gj], r[i * (i + 1) / 2 + j]);
                }
                atomicAdd(&d_acc[g][NPAIR + q * 4 + i], r[10 + i]);
            }
        } else {
            for (int i = 0; i < 4; i++)
                for (int j = 0; j < 4; j++) {
                    const int gi = qi * 4 + i, gj = qj * 4 + j;
                    atomicAdd(&d_acc[g][gi * (gi + 1) / 2 + gj], r[i * 4 + j]);
                }
        }
    }
}

// ---------------------------------------------------------------------------
// Solve: one block per group, 16 threads, everything in shared memory, fp64.
__global__ void __launch_bounds__(16) solve_kernel() {
    const int g = blockIdx.x;
    const int t = threadIdx.x;
    __shared__ double P[GS][GS + 1];
    __shared__ double L[GS][GS + 1];
    __shared__ double V[GS][GS + 1];
    __shared__ double m[GS];

    const double Nd   = (double)BATCH * (double)HW;
    const double EPSd = 1e-3;
    const unsigned MASK = 0xffffu;

    m[t] = (double)d_acc[g][NPAIR + t] / Nd;
    __syncwarp(MASK);

    for (int j = 0; j < GS; j++) {
        const int i_ = t > j ? t : j, j_ = t > j ? j : t;
        double c = (double)d_acc[g][i_ * (i_ + 1) / 2 + j_] / Nd - m[t] * m[j];
        c *= (1.0 - EPSd);
        if (t == j) c += EPSd;
        P[t][j] = c;
    }
    __syncwarp(MASK);

    for (int j = 0; j < GS; j++) {
        if (t == j) {
            double s = P[j][j];
            for (int k = 0; k < j; k++) s -= L[j][k] * L[j][k];
            L[j][j] = sqrt(s);
        }
        __syncwarp(MASK);
        if (t > j) {
            double s = P[t][j];
            for (int k = 0; k < j; k++) s -= L[t][k] * L[j][k];
            L[t][j] = s / L[j][j];
        }
        __syncwarp(MASK);
    }

    V[t][t] = 1.0 / L[t][t];
    for (int i = t + 1; i < GS; i++) {
        double s = 0.0;
        for (int k = t; k < i; k++) s += L[i][k] * V[k][t];
        V[i][t] = -s / L[i][i];
    }
    __syncwarp(MASK);

    double bsum = 0.0;
    for (int j = 0; j <= t; j++) {
        d_Linv[g][t * (t + 1) / 2 + j] = (float)V[t][j];
        bsum += V[t][j] * m[j];
    }
    d_bias[g * GS + t] = (float)bsum;
}

// ---------------------------------------------------------------------------
// Apply (unchanged, proven ~65us / 69% DRAM):
// out_i = sum_{j<=i} Linv_ij * x_j - bias_i, float4, streaming stores.
__global__ void __launch_bounds__(256, 2) apply_kernel(const float* __restrict__ x,
                                                       float* __restrict__ out) {
    const int g = blockIdx.x & 31;
    const int b = blockIdx.x >> 5;

    __shared__ float Ls[NPAIR];
    __shared__ float bs[GS];
    if (threadIdx.x < NPAIR) Ls[threadIdx.x] = d_Linv[g][threadIdx.x];
    if (threadIdx.x < GS)    bs[threadIdx.x] = d_bias[g * GS + threadIdx.x];
    __syncthreads();

    const size_t off = ((size_t)b * CH + (size_t)g * GS) * HW;
    const float4* in = (const float4*)(x + off);
    float4*       op = (float4*)(out + off);

    for (int pos = threadIdx.x; pos < HW4; pos += 256) {
        float4 v[GS];
#pragma unroll
        for (int c = 0; c < GS; c++) v[c] = in[(size_t)c * HW4 + pos];
#pragma unroll
        for (int i = 0; i < GS; i++) {
            const float bias = bs[i];
            float4 a;
            a.x = -bias; a.y = -bias; a.z = -bias; a.w = -bias;
#pragma unroll
            for (int j = 0; j <= i; j++) {
                const float f = Ls[i * (i + 1) / 2 + j];
                a.x = fmaf(f, v[j].x, a.x);
                a.y = fmaf(f, v[j].y, a.y);
                a.z = fmaf(f, v[j].z, a.z);
                a.w = fmaf(f, v[j].w, a.w);
            }
            __stcs(&op[(size_t)i * HW4 + pos], a);
        }
    }
}

// ---------------------------------------------------------------------------
extern "C" void kernel_launch(void* const* d_in, const int* in_sizes, int n_in,
                              void* d_out, int out_size) {
    const float* x   = (const float*)d_in[0];
    float*       out = (float*)d_out;

    zero_kernel<<<(GROUPS * NACC + 255) / 256, 256>>>();
    stats_kernel<<<GROUPS * BATCH, STATS_T>>>(x);
    solve_kernel<<<GROUPS, 16>>>();
    apply_kernel<<<GROUPS * BATCH, 256>>>(x, out);
}